// round 1
// baseline (speedup 1.0000x reference)
#include <cuda_runtime.h>
#include <cuda_bf16.h>

// LinearQuant: q = clip(floor(x/delta + 0.5), -2^(bits-1), 2^(bits-1)-1) * delta
// bits=8, sf=4 -> delta = 1/16, bound = 128.
// Pure streaming elementwise op: HBM-bound. float4 vectorized, one pass.

__device__ __forceinline__ float quant1(float x) {
    // floor(x * 16 + 0.5), clamp to [-128, 127], * (1/16)
    float q = floorf(fmaf(x, 16.0f, 0.5f));
    q = fminf(fmaxf(q, -128.0f), 127.0f);
    return q * 0.0625f;
}

__global__ void __launch_bounds__(256) linquant_vec4_kernel(
    const float4* __restrict__ in, float4* __restrict__ out, int n4)
{
    int i = blockIdx.x * blockDim.x + threadIdx.x;
    if (i < n4) {
        float4 v = in[i];
        float4 r;
        r.x = quant1(v.x);
        r.y = quant1(v.y);
        r.z = quant1(v.z);
        r.w = quant1(v.w);
        out[i] = r;
    }
}

__global__ void __launch_bounds__(256) linquant_tail_kernel(
    const float* __restrict__ in, float* __restrict__ out, int start, int n)
{
    int i = start + blockIdx.x * blockDim.x + threadIdx.x;
    if (i < n) {
        out[i] = quant1(in[i]);
    }
}

extern "C" void kernel_launch(void* const* d_in, const int* in_sizes, int n_in,
                              void* d_out, int out_size) {
    const float* in = (const float*)d_in[0];
    float* out = (float*)d_out;
    int n = in_sizes[0];

    int n4 = n / 4;
    if (n4 > 0) {
        int threads = 256;
        int blocks = (n4 + threads - 1) / threads;
        linquant_vec4_kernel<<<blocks, threads>>>(
            (const float4*)in, (float4*)out, n4);
    }
    int rem = n - n4 * 4;
    if (rem > 0) {
        linquant_tail_kernel<<<1, 256>>>(in, out, n4 * 4, n);
    }
}

// round 2
// speedup vs baseline: 1.0262x; 1.0262x over previous
#include <cuda_runtime.h>
#include <cuda_bf16.h>

// LinearQuant: q = clip(floor(x*16 + 0.5), -128, 127) / 16.  HBM-bound stream.
// R2: 4x float4 per thread, front-batched loads (MLP=4/thread), streaming
// cache hints (.cs) since working set (411MB) >> L2 (126MB).

__device__ __forceinline__ float quant1(float x) {
    float q = floorf(fmaf(x, 16.0f, 0.5f));
    q = fminf(fmaxf(q, -128.0f), 127.0f);
    return q * 0.0625f;
}

__device__ __forceinline__ float4 quant4(float4 v) {
    float4 r;
    r.x = quant1(v.x); r.y = quant1(v.y);
    r.z = quant1(v.z); r.w = quant1(v.w);
    return r;
}

#define VPT 4  // float4 vectors per thread

__global__ void __launch_bounds__(256) linquant_vec4x4_kernel(
    const float4* __restrict__ in, float4* __restrict__ out, int n4)
{
    int base = blockIdx.x * (blockDim.x * VPT) + threadIdx.x;

    // Fast path: whole 4-batch in range (true for all full blocks).
    if (base + 3 * blockDim.x < n4) {
        float4 v0 = __ldcs(&in[base + 0 * blockDim.x]);
        float4 v1 = __ldcs(&in[base + 1 * blockDim.x]);
        float4 v2 = __ldcs(&in[base + 2 * blockDim.x]);
        float4 v3 = __ldcs(&in[base + 3 * blockDim.x]);
        __stcs(&out[base + 0 * blockDim.x], quant4(v0));
        __stcs(&out[base + 1 * blockDim.x], quant4(v1));
        __stcs(&out[base + 2 * blockDim.x], quant4(v2));
        __stcs(&out[base + 3 * blockDim.x], quant4(v3));
    } else {
        #pragma unroll
        for (int k = 0; k < VPT; k++) {
            int i = base + k * blockDim.x;
            if (i < n4) {
                __stcs(&out[i], quant4(__ldcs(&in[i])));
            }
        }
    }
}

__global__ void __launch_bounds__(256) linquant_tail_kernel(
    const float* __restrict__ in, float* __restrict__ out, int start, int n)
{
    int i = start + blockIdx.x * blockDim.x + threadIdx.x;
    if (i < n) {
        out[i] = quant1(in[i]);
    }
}

extern "C" void kernel_launch(void* const* d_in, const int* in_sizes, int n_in,
                              void* d_out, int out_size) {
    const float* in = (const float*)d_in[0];
    float* out = (float*)d_out;
    int n = in_sizes[0];

    int n4 = n / 4;
    if (n4 > 0) {
        const int threads = 256;
        const int per_block = threads * VPT;
        int blocks = (n4 + per_block - 1) / per_block;
        linquant_vec4x4_kernel<<<blocks, threads>>>(
            (const float4*)in, (float4*)out, n4);
    }
    int rem = n - n4 * 4;
    if (rem > 0) {
        linquant_tail_kernel<<<1, 256>>>(in, out, n4 * 4, n);
    }
}

// round 3
// speedup vs baseline: 1.0313x; 1.0049x over previous
#include <cuda_runtime.h>
#include <cuda_bf16.h>
#include <cstdint>

// LinearQuant: q = clip(floor(x*16 + 0.5), -128, 127) / 16.  HBM-bound stream.
// R3: sm_100a 256-bit vector ld/st (ld.global.cs.v8.f32), 4x 32B per thread
// front-batched. Streaming (.cs) hints: working set 411MB >> 126MB L2.

__device__ __forceinline__ float quant1(float x) {
    float q = floorf(fmaf(x, 16.0f, 0.5f));
    q = fminf(fmaxf(q, -128.0f), 127.0f);
    return q * 0.0625f;
}

__device__ __forceinline__ void ld_v8_cs(const float* p, float r[8]) {
    asm volatile(
        "ld.global.cs.v8.f32 {%0,%1,%2,%3,%4,%5,%6,%7}, [%8];"
        : "=f"(r[0]), "=f"(r[1]), "=f"(r[2]), "=f"(r[3]),
          "=f"(r[4]), "=f"(r[5]), "=f"(r[6]), "=f"(r[7])
        : "l"(p));
}

__device__ __forceinline__ void st_v8_cs(float* p, const float r[8]) {
    asm volatile(
        "st.global.cs.v8.f32 [%0], {%1,%2,%3,%4,%5,%6,%7,%8};"
        :: "l"(p),
           "f"(r[0]), "f"(r[1]), "f"(r[2]), "f"(r[3]),
           "f"(r[4]), "f"(r[5]), "f"(r[6]), "f"(r[7])
        : "memory");
}

#define VPT 4  // 32B chunks per thread (128B/thread total)

__global__ void __launch_bounds__(256) linquant_v8_kernel(
    const float* __restrict__ in, float* __restrict__ out, int n8)
{
    // index in units of 8 floats (32B)
    int base = blockIdx.x * (blockDim.x * VPT) + threadIdx.x;

    if (base + 3 * blockDim.x < n8) {
        float v0[8], v1[8], v2[8], v3[8];
        ld_v8_cs(in + (size_t)(base + 0 * blockDim.x) * 8, v0);
        ld_v8_cs(in + (size_t)(base + 1 * blockDim.x) * 8, v1);
        ld_v8_cs(in + (size_t)(base + 2 * blockDim.x) * 8, v2);
        ld_v8_cs(in + (size_t)(base + 3 * blockDim.x) * 8, v3);
        #pragma unroll
        for (int j = 0; j < 8; j++) v0[j] = quant1(v0[j]);
        #pragma unroll
        for (int j = 0; j < 8; j++) v1[j] = quant1(v1[j]);
        #pragma unroll
        for (int j = 0; j < 8; j++) v2[j] = quant1(v2[j]);
        #pragma unroll
        for (int j = 0; j < 8; j++) v3[j] = quant1(v3[j]);
        st_v8_cs(out + (size_t)(base + 0 * blockDim.x) * 8, v0);
        st_v8_cs(out + (size_t)(base + 1 * blockDim.x) * 8, v1);
        st_v8_cs(out + (size_t)(base + 2 * blockDim.x) * 8, v2);
        st_v8_cs(out + (size_t)(base + 3 * blockDim.x) * 8, v3);
    } else {
        #pragma unroll
        for (int k = 0; k < VPT; k++) {
            int i8 = base + k * blockDim.x;
            if (i8 < n8) {
                float v[8];
                ld_v8_cs(in + (size_t)i8 * 8, v);
                #pragma unroll
                for (int j = 0; j < 8; j++) v[j] = quant1(v[j]);
                st_v8_cs(out + (size_t)i8 * 8, v);
            }
        }
    }
}

__global__ void __launch_bounds__(256) linquant_tail_kernel(
    const float* __restrict__ in, float* __restrict__ out, int start, int n)
{
    int i = start + blockIdx.x * blockDim.x + threadIdx.x;
    if (i < n) {
        out[i] = quant1(in[i]);
    }
}

extern "C" void kernel_launch(void* const* d_in, const int* in_sizes, int n_in,
                              void* d_out, int out_size) {
    const float* in = (const float*)d_in[0];
    float* out = (float*)d_out;
    int n = in_sizes[0];

    int n8 = n / 8;
    if (n8 > 0) {
        const int threads = 256;
        const int per_block = threads * VPT;  // in 8-float units
        int blocks = (n8 + per_block - 1) / per_block;
        linquant_v8_kernel<<<blocks, threads>>>(in, out, n8);
    }
    int rem = n - n8 * 8;
    if (rem > 0) {
        linquant_tail_kernel<<<1, 256>>>(in, out, n8 * 8, n);
    }
}